// round 1
// baseline (speedup 1.0000x reference)
#include <cuda_runtime.h>
#include <cuda_bf16.h>
#include <math.h>

// Problem constants
#define B_   8
#define S_   1024
#define D_   768
#define H_   12
#define L_   8
#define DH_  64
#define V_   1024
#define COND_ 256
#define BS_  (B_ * S_)          // 8192
#define BSD_ (B_ * S_ * D_)     // 6291456

// ---------------- scratch (static device arrays; no allocation allowed) ----
__device__ float d_x[BSD_];
__device__ float d_h[BSD_];
__device__ float d_q[BSD_];
__device__ float d_k[BSD_];
__device__ float d_v[BSD_];
__device__ float d_o[BSD_];
__device__ float d_mlp[B_ * S_ * 4 * D_];   // 25165824
__device__ float d_a[B_ * COND_];
__device__ float d_g[B_ * D_];
__device__ float d_bb[B_ * D_];

// ---------------- embedding + sinusoidal PE --------------------------------
__global__ void embed_kernel(const int* __restrict__ tokens,
                             const float* __restrict__ emb,
                             float* __restrict__ x) {
    int row = blockIdx.x;              // b*S + s
    int s = row & (S_ - 1);
    int tok = tokens[row];
    const float* er = emb + (size_t)tok * D_;
    float* xr = x + (size_t)row * D_;
    const float c0 = -9.210340371976184f / (float)D_;  // -ln(10000)/D
    for (int c = threadIdx.x; c < D_; c += blockDim.x) {
        int base = c & ~1;
        float div = __expf((float)base * c0);
        float ang = (float)s * div;
        float pe = (c & 1) ? cosf(ang) : sinf(ang);
        xr[c] = er[c] + pe;
    }
}

// ---------------- action embedding gather ----------------------------------
__global__ void act_kernel(const int* __restrict__ actions,
                           const float* __restrict__ act_emb,
                           float* __restrict__ a) {
    int b = blockIdx.x;
    int t = threadIdx.x;               // 0..255
    int j = t >> 6, d = t & 63;
    int idx = actions[b * 4 + j];
    a[b * COND_ + t] = act_emb[idx * 64 + d];
}

// ---------------- conditional gain/shift: g = a@gw, bb = a@bw --------------
__global__ void condmod_kernel(const float* __restrict__ a,
                               const float* __restrict__ gw,
                               const float* __restrict__ bw,
                               float* __restrict__ g,
                               float* __restrict__ bb) {
    int idx = blockIdx.x * blockDim.x + threadIdx.x;    // < B*D = 6144
    int b = idx / D_, d = idx % D_;
    const float* av = a + b * COND_;
    float sg = 0.f, sb = 0.f;
    #pragma unroll 4
    for (int c = 0; c < COND_; c++) {
        float x = av[c];
        sg += x * gw[c * D_ + d];
        sb += x * bw[c * D_ + d];
    }
    g[idx] = sg;
    bb[idx] = sb;
}

// ---------------- conditional layernorm ------------------------------------
__global__ void ln_kernel(const float* __restrict__ x,
                          const float* __restrict__ g,
                          const float* __restrict__ bb,
                          float* __restrict__ out) {
    int row = blockIdx.x;
    int b = row >> 10;   // row / S
    const float* xr = x + (size_t)row * D_;
    float v[3];
    float s = 0.f, s2 = 0.f;
    #pragma unroll
    for (int i = 0; i < 3; i++) {
        v[i] = xr[threadIdx.x + i * 256];
        s += v[i];
        s2 += v[i] * v[i];
    }
    #pragma unroll
    for (int o = 16; o > 0; o >>= 1) {
        s  += __shfl_xor_sync(0xffffffffu, s, o);
        s2 += __shfl_xor_sync(0xffffffffu, s2, o);
    }
    __shared__ float rs[8], rs2[8];
    int w = threadIdx.x >> 5, ln = threadIdx.x & 31;
    if (ln == 0) { rs[w] = s; rs2[w] = s2; }
    __syncthreads();
    if (threadIdx.x < 32) {
        float a1 = (ln < 8) ? rs[ln] : 0.f;
        float a2 = (ln < 8) ? rs2[ln] : 0.f;
        #pragma unroll
        for (int o = 4; o > 0; o >>= 1) {
            a1 += __shfl_xor_sync(0xffffffffu, a1, o);
            a2 += __shfl_xor_sync(0xffffffffu, a2, o);
        }
        if (ln == 0) { rs[0] = a1; rs2[0] = a2; }
    }
    __syncthreads();
    float mean = rs[0] * (1.f / D_);
    float var  = rs2[0] * (1.f / D_) - mean * mean;
    float rstd = rsqrtf(var + 1e-5f);
    const float* gr = g + (size_t)b * D_;
    const float* br = bb + (size_t)b * D_;
    float* orow = out + (size_t)row * D_;
    #pragma unroll
    for (int i = 0; i < 3; i++) {
        int c = threadIdx.x + i * 256;
        orow[c] = (v[i] - mean) * rstd * gr[c] + br[c];
    }
}

// ---------------- per-head QKV projection (64x64 GEMM, batched) ------------
__global__ __launch_bounds__(256) void qkv_kernel(
        const float* __restrict__ Hx,
        const float* __restrict__ Wq, const float* __restrict__ Wk,
        const float* __restrict__ Wv,
        float* __restrict__ q, float* __restrict__ k, float* __restrict__ v) {
    __shared__ float As[16][64];
    __shared__ float Ws[16][64];
    int head = blockIdx.y, proj = blockIdx.z;
    const float* W = (proj == 0 ? Wq : (proj == 1 ? Wk : Wv)) + head * 4096;
    float* out = (proj == 0 ? q : (proj == 1 ? k : v));
    const float* Ab = Hx + (size_t)blockIdx.x * 64 * D_ + head * 64;
    int tid = threadIdx.x, ty = tid >> 4, tx = tid & 15;
    float c[4][4] = {};
    for (int k0 = 0; k0 < 64; k0 += 16) {
        int arow = tid >> 2, acol = (tid & 3) << 2;
        float4 va = *(const float4*)(Ab + (size_t)arow * D_ + k0 + acol);
        As[acol + 0][arow] = va.x; As[acol + 1][arow] = va.y;
        As[acol + 2][arow] = va.z; As[acol + 3][arow] = va.w;
        int wrow = tid >> 4, wcol = (tid & 15) << 2;
        *(float4*)&Ws[wrow][wcol] = *(const float4*)(W + (k0 + wrow) * 64 + wcol);
        __syncthreads();
        #pragma unroll
        for (int kk = 0; kk < 16; kk++) {
            float a[4], bfr[4];
            *(float4*)a   = *(float4*)&As[kk][ty * 4];
            *(float4*)bfr = *(float4*)&Ws[kk][tx * 4];
            #pragma unroll
            for (int i = 0; i < 4; i++)
                #pragma unroll
                for (int j = 0; j < 4; j++)
                    c[i][j] += a[i] * bfr[j];
        }
        __syncthreads();
    }
    #pragma unroll
    for (int i = 0; i < 4; i++) {
        int m = blockIdx.x * 64 + ty * 4 + i;
        float* orow = out + (size_t)m * D_ + head * 64 + tx * 4;
        #pragma unroll
        for (int j = 0; j < 4; j++) orow[j] = c[i][j];
    }
}

// ---------------- flash attention (no mask, full softmax) ------------------
#define FPAD 65
__global__ __launch_bounds__(256) void flash_kernel(
        const float* __restrict__ Q, const float* __restrict__ K,
        const float* __restrict__ V, float* __restrict__ O) {
    extern __shared__ float sm[];
    float* Qs  = sm;
    float* KVs = sm + 64 * FPAD;
    float* Ps  = sm + 2 * 64 * FPAD;
    int bh = blockIdx.y;
    int b = bh / H_, h = bh % H_;
    size_t base = (size_t)b * S_ * D_ + h * 64;
    int t0 = blockIdx.x * 64;
    int tid = threadIdx.x, ty = tid >> 4, tx = tid & 15;

    for (int i = tid; i < 4096; i += 256) {
        int r = i >> 6, c = i & 63;
        Qs[r * FPAD + c] = Q[base + (size_t)(t0 + r) * D_ + c];
    }
    float acc[4][4] = {};
    float rM[4], rL[4];
    #pragma unroll
    for (int i = 0; i < 4; i++) { rM[i] = -1e30f; rL[i] = 0.f; }

    for (int kt = 0; kt < 16; kt++) {
        __syncthreads();
        int k0 = kt * 64;
        for (int i = tid; i < 4096; i += 256) {
            int r = i >> 6, c = i & 63;
            KVs[r * FPAD + c] = K[base + (size_t)(k0 + r) * D_ + c];
        }
        __syncthreads();
        float sc[4][4] = {};
        #pragma unroll 8
        for (int kk = 0; kk < 64; kk++) {
            float qr[4], kr[4];
            #pragma unroll
            for (int i = 0; i < 4; i++) qr[i] = Qs[(ty + 16 * i) * FPAD + kk];
            #pragma unroll
            for (int j = 0; j < 4; j++) kr[j] = KVs[(tx + 16 * j) * FPAD + kk];
            #pragma unroll
            for (int i = 0; i < 4; i++)
                #pragma unroll
                for (int j = 0; j < 4; j++)
                    sc[i][j] += qr[i] * kr[j];
        }
        #pragma unroll
        for (int i = 0; i < 4; i++)
            #pragma unroll
            for (int j = 0; j < 4; j++)
                sc[i][j] *= 0.125f;
        // online softmax
        float tmax[4];
        #pragma unroll
        for (int i = 0; i < 4; i++) {
            float m = sc[i][0];
            #pragma unroll
            for (int j = 1; j < 4; j++) m = fmaxf(m, sc[i][j]);
            #pragma unroll
            for (int o = 8; o > 0; o >>= 1)
                m = fmaxf(m, __shfl_xor_sync(0xffffffffu, m, o));
            tmax[i] = m;
        }
        float al[4], tsum[4];
        #pragma unroll
        for (int i = 0; i < 4; i++) {
            float nM = fmaxf(rM[i], tmax[i]);
            al[i] = expf(rM[i] - nM);
            rM[i] = nM;
            float ls = 0.f;
            #pragma unroll
            for (int j = 0; j < 4; j++) {
                float p = expf(sc[i][j] - nM);
                Ps[(ty + 16 * i) * FPAD + tx + 16 * j] = p;
                ls += p;
            }
            #pragma unroll
            for (int o = 8; o > 0; o >>= 1)
                ls += __shfl_xor_sync(0xffffffffu, ls, o);
            tsum[i] = ls;
        }
        #pragma unroll
        for (int i = 0; i < 4; i++) {
            rL[i] = rL[i] * al[i] + tsum[i];
            #pragma unroll
            for (int j = 0; j < 4; j++) acc[i][j] *= al[i];
        }
        __syncthreads();
        for (int i = tid; i < 4096; i += 256) {
            int r = i >> 6, c = i & 63;
            KVs[r * FPAD + c] = V[base + (size_t)(k0 + r) * D_ + c];
        }
        __syncthreads();
        #pragma unroll 8
        for (int n = 0; n < 64; n++) {
            float pr[4], vr[4];
            #pragma unroll
            for (int i = 0; i < 4; i++) pr[i] = Ps[(ty + 16 * i) * FPAD + n];
            #pragma unroll
            for (int j = 0; j < 4; j++) vr[j] = KVs[n * FPAD + tx + 16 * j];
            #pragma unroll
            for (int i = 0; i < 4; i++)
                #pragma unroll
                for (int j = 0; j < 4; j++)
                    acc[i][j] += pr[i] * vr[j];
        }
    }
    #pragma unroll
    for (int i = 0; i < 4; i++) {
        float inv = 1.f / rL[i];
        #pragma unroll
        for (int j = 0; j < 4; j++)
            O[base + (size_t)(t0 + ty + 16 * i) * D_ + tx + 16 * j] = acc[i][j] * inv;
    }
}

// ---------------- big SGEMM: C(op)= A[M,K]@B[K,N] + bias -------------------
// EPI: 0 = store, 1 = gelu(tanh) store, 2 = add into C (residual)
template <int EPI>
__global__ __launch_bounds__(256) void gemm128_kernel(
        const float* __restrict__ A, const float* __restrict__ Bm,
        const float* __restrict__ bias, float* __restrict__ C,
        int N, int K) {
    __shared__ float As[16][128];
    __shared__ float Bs[16][128];
    int tid = threadIdx.x, ty = tid >> 4, tx = tid & 15;
    const float* Ab = A + (size_t)blockIdx.x * 128 * K;
    const float* Bb = Bm + (size_t)blockIdx.y * 128;
    float c[8][8] = {};
    for (int k0 = 0; k0 < K; k0 += 16) {
        #pragma unroll
        for (int r = 0; r < 2; r++) {
            int f = tid * 2 + r;
            int arow = f >> 2, acol = (f & 3) << 2;
            float4 va = *(const float4*)(Ab + (size_t)arow * K + k0 + acol);
            As[acol + 0][arow] = va.x; As[acol + 1][arow] = va.y;
            As[acol + 2][arow] = va.z; As[acol + 3][arow] = va.w;
            int brow = f >> 5, bcol = (f & 31) << 2;
            *(float4*)&Bs[brow][bcol] =
                *(const float4*)(Bb + (size_t)(k0 + brow) * N + bcol);
        }
        __syncthreads();
        #pragma unroll
        for (int kk = 0; kk < 16; kk++) {
            float a[8], bfr[8];
            *(float4*)&a[0]   = *(float4*)&As[kk][ty * 4];
            *(float4*)&a[4]   = *(float4*)&As[kk][ty * 4 + 64];
            *(float4*)&bfr[0] = *(float4*)&Bs[kk][tx * 4];
            *(float4*)&bfr[4] = *(float4*)&Bs[kk][tx * 4 + 64];
            #pragma unroll
            for (int i = 0; i < 8; i++)
                #pragma unroll
                for (int j = 0; j < 8; j++)
                    c[i][j] += a[i] * bfr[j];
        }
        __syncthreads();
    }
    #pragma unroll
    for (int i = 0; i < 8; i++) {
        int m = blockIdx.x * 128 + ty * 4 + (i & 3) + ((i >> 2) << 6);
        #pragma unroll
        for (int j = 0; j < 8; j++) {
            int n = blockIdx.y * 128 + tx * 4 + (j & 3) + ((j >> 2) << 6);
            float val = c[i][j] + bias[n];
            size_t idx = (size_t)m * N + n;
            if (EPI == 0) {
                C[idx] = val;
            } else if (EPI == 1) {
                float t = 0.7978845608028654f * (val + 0.044715f * val * val * val);
                C[idx] = 0.5f * val * (1.f + tanhf(t));
            } else {
                C[idx] += val;
            }
        }
    }
}

// ---------------- host driver ----------------------------------------------
extern "C" void kernel_launch(void* const* d_in, const int* in_sizes, int n_in,
                              void* d_out, int out_size) {
    const int*   tokens  = (const int*)d_in[0];
    const int*   actions = (const int*)d_in[1];
    const float* emb     = (const float*)d_in[2];
    const float* act_emb = (const float*)d_in[3];
    const float* ln1_g   = (const float*)d_in[4];
    const float* ln1_b   = (const float*)d_in[5];
    const float* Wq      = (const float*)d_in[6];
    const float* Wk      = (const float*)d_in[7];
    const float* Wv      = (const float*)d_in[8];
    const float* Wo      = (const float*)d_in[9];
    const float* bo      = (const float*)d_in[10];
    const float* ln2_g   = (const float*)d_in[11];
    const float* ln2_b   = (const float*)d_in[12];
    const float* W1      = (const float*)d_in[13];
    const float* b1      = (const float*)d_in[14];
    const float* W2      = (const float*)d_in[15];
    const float* b2      = (const float*)d_in[16];
    const float* lnf_g   = (const float*)d_in[17];
    const float* lnf_b   = (const float*)d_in[18];
    const float* Wout    = (const float*)d_in[19];
    const float* bout    = (const float*)d_in[20];
    float* out = (float*)d_out;

    float *x, *h, *q, *k, *v, *o, *mlp, *a, *g, *bb;
    cudaGetSymbolAddress((void**)&x,  d_x);
    cudaGetSymbolAddress((void**)&h,  d_h);
    cudaGetSymbolAddress((void**)&q,  d_q);
    cudaGetSymbolAddress((void**)&k,  d_k);
    cudaGetSymbolAddress((void**)&v,  d_v);
    cudaGetSymbolAddress((void**)&o,  d_o);
    cudaGetSymbolAddress((void**)&mlp, d_mlp);
    cudaGetSymbolAddress((void**)&a,  d_a);
    cudaGetSymbolAddress((void**)&g,  d_g);
    cudaGetSymbolAddress((void**)&bb, d_bb);

    const int flash_smem = 3 * 64 * FPAD * (int)sizeof(float);  // 49920
    cudaFuncSetAttribute(flash_kernel,
                         cudaFuncAttributeMaxDynamicSharedMemorySize, flash_smem);

    embed_kernel<<<BS_, 256>>>(tokens, emb, x);
    act_kernel<<<B_, 256>>>(actions, act_emb, a);

    const int lnSz  = COND_ * D_;        // 196608
    const int wqSz  = H_ * DH_ * DH_;    // 49152
    const int woSz  = D_ * D_;           // 589824
    const int w1Sz  = D_ * 4 * D_;       // 2359296

    for (int l = 0; l < L_; l++) {
        condmod_kernel<<<24, 256>>>(a, ln1_g + (size_t)l * lnSz,
                                    ln1_b + (size_t)l * lnSz, g, bb);
        ln_kernel<<<BS_, 256>>>(x, g, bb, h);
        qkv_kernel<<<dim3(BS_ / 64, H_, 3), 256>>>(
            h, Wq + (size_t)l * wqSz, Wk + (size_t)l * wqSz,
            Wv + (size_t)l * wqSz, q, k, v);
        flash_kernel<<<dim3(S_ / 64, B_ * H_), 256, flash_smem>>>(q, k, v, o);
        gemm128_kernel<2><<<dim3(BS_ / 128, D_ / 128), 256>>>(
            o, Wo + (size_t)l * woSz, bo + (size_t)l * D_, x, D_, D_);
        condmod_kernel<<<24, 256>>>(a, ln2_g + (size_t)l * lnSz,
                                    ln2_b + (size_t)l * lnSz, g, bb);
        ln_kernel<<<BS_, 256>>>(x, g, bb, h);
        gemm128_kernel<1><<<dim3(BS_ / 128, 4 * D_ / 128), 256>>>(
            h, W1 + (size_t)l * w1Sz, b1 + (size_t)l * 4 * D_, mlp, 4 * D_, D_);
        gemm128_kernel<2><<<dim3(BS_ / 128, D_ / 128), 256>>>(
            mlp, W2 + (size_t)l * w1Sz, b2 + (size_t)l * D_, x, D_, 4 * D_);
    }
    condmod_kernel<<<24, 256>>>(a, lnf_g, lnf_b, g, bb);
    ln_kernel<<<BS_, 256>>>(x, g, bb, h);
    gemm128_kernel<0><<<dim3(BS_ / 128, V_ / 128), 256>>>(
        h, Wout, bout, out, V_, D_);
}

// round 4
// speedup vs baseline: 1.7826x; 1.7826x over previous
#include <cuda_runtime.h>
#include <cuda_bf16.h>
#include <math.h>
#include <stdint.h>
#include <cstdint>

// Problem constants
#define B_   8
#define S_   1024
#define D_   768
#define H_   12
#define L_   8
#define DH_  64
#define V_   1024
#define COND_ 256
#define BS_  (B_ * S_)          // 8192
#define BSD_ (B_ * S_ * D_)     // 6291456

// ---------------- scratch (static device arrays; no allocation allowed) ----
__device__ float d_x[BSD_];
__device__ float d_h[BSD_];
__device__ float d_q[BSD_];
__device__ float d_k[BSD_];
__device__ float d_v[BSD_];
__device__ float d_o[BSD_];
__device__ float d_mlp[B_ * S_ * 4 * D_];   // 25165824
__device__ float d_a[B_ * COND_];
__device__ float d_g[B_ * D_];
__device__ float d_bb[B_ * D_];

// ---------------- embedding + sinusoidal PE --------------------------------
__global__ void embed_kernel(const int* __restrict__ tokens,
                             const float* __restrict__ emb,
                             float* __restrict__ x) {
    int row = blockIdx.x;              // b*S + s
    int s = row & (S_ - 1);
    int tok = tokens[row];
    const float* er = emb + (size_t)tok * D_;
    float* xr = x + (size_t)row * D_;
    const float c0 = -9.210340371976184f / (float)D_;  // -ln(10000)/D
    for (int c = threadIdx.x; c < D_; c += blockDim.x) {
        int base = c & ~1;
        float div = __expf((float)base * c0);
        float ang = (float)s * div;
        float pe = (c & 1) ? cosf(ang) : sinf(ang);
        xr[c] = er[c] + pe;
    }
}

// ---------------- action embedding gather ----------------------------------
__global__ void act_kernel(const int* __restrict__ actions,
                           const float* __restrict__ act_emb,
                           float* __restrict__ a) {
    int b = blockIdx.x;
    int t = threadIdx.x;               // 0..255
    int j = t >> 6, d = t & 63;
    int idx = actions[b * 4 + j];
    a[b * COND_ + t] = act_emb[idx * 64 + d];
}

// ---------------- conditional gain/shift: g = a@gw, bb = a@bw --------------
__global__ void condmod_kernel(const float* __restrict__ a,
                               const float* __restrict__ gw,
                               const float* __restrict__ bw,
                               float* __restrict__ g,
                               float* __restrict__ bb) {
    __shared__ float as_[COND_];
    int b = blockIdx.y;
    int d = blockIdx.x * 256 + threadIdx.x;
    if (threadIdx.x < COND_) as_[threadIdx.x] = a[b * COND_ + threadIdx.x];
    __syncthreads();
    float sg = 0.f, sb = 0.f;
    #pragma unroll 8
    for (int c = 0; c < COND_; c++) {
        float x = as_[c];
        sg += x * gw[c * D_ + d];
        sb += x * bw[c * D_ + d];
    }
    g[b * D_ + d] = sg;
    bb[b * D_ + d] = sb;
}

// ---------------- conditional layernorm ------------------------------------
__global__ void ln_kernel(const float* __restrict__ x,
                          const float* __restrict__ g,
                          const float* __restrict__ bb,
                          float* __restrict__ out) {
    int row = blockIdx.x;
    int b = row >> 10;   // row / S
    const float* xr = x + (size_t)row * D_;
    float v[3];
    float s = 0.f, s2 = 0.f;
    #pragma unroll
    for (int i = 0; i < 3; i++) {
        v[i] = xr[threadIdx.x + i * 256];
        s += v[i];
        s2 += v[i] * v[i];
    }
    #pragma unroll
    for (int o = 16; o > 0; o >>= 1) {
        s  += __shfl_xor_sync(0xffffffffu, s, o);
        s2 += __shfl_xor_sync(0xffffffffu, s2, o);
    }
    __shared__ float rs[8], rs2[8];
    int w = threadIdx.x >> 5, ln = threadIdx.x & 31;
    if (ln == 0) { rs[w] = s; rs2[w] = s2; }
    __syncthreads();
    if (threadIdx.x < 32) {
        float a1 = (ln < 8) ? rs[ln] : 0.f;
        float a2 = (ln < 8) ? rs2[ln] : 0.f;
        #pragma unroll
        for (int o = 4; o > 0; o >>= 1) {
            a1 += __shfl_xor_sync(0xffffffffu, a1, o);
            a2 += __shfl_xor_sync(0xffffffffu, a2, o);
        }
        if (ln == 0) { rs[0] = a1; rs2[0] = a2; }
    }
    __syncthreads();
    float mean = rs[0] * (1.f / D_);
    float var  = rs2[0] * (1.f / D_) - mean * mean;
    float rstd = rsqrtf(var + 1e-5f);
    const float* gr = g + (size_t)b * D_;
    const float* br = bb + (size_t)b * D_;
    float* orow = out + (size_t)row * D_;
    #pragma unroll
    for (int i = 0; i < 3; i++) {
        int c = threadIdx.x + i * 256;
        orow[c] = (v[i] - mean) * rstd * gr[c] + br[c];
    }
}

// ---------------- per-head QKV projection (64x64 GEMM, batched) ------------
__global__ __launch_bounds__(256) void qkv_kernel(
        const float* __restrict__ Hx,
        const float* __restrict__ Wq, const float* __restrict__ Wk,
        const float* __restrict__ Wv,
        float* __restrict__ q, float* __restrict__ k, float* __restrict__ v) {
    __shared__ float As[16][64];
    __shared__ float Ws[16][64];
    int head = blockIdx.y, proj = blockIdx.z;
    const float* W = (proj == 0 ? Wq : (proj == 1 ? Wk : Wv)) + head * 4096;
    float* out = (proj == 0 ? q : (proj == 1 ? k : v));
    const float* Ab = Hx + (size_t)blockIdx.x * 64 * D_ + head * 64;
    int tid = threadIdx.x, ty = tid >> 4, tx = tid & 15;
    float c[4][4] = {};
    for (int k0 = 0; k0 < 64; k0 += 16) {
        int arow = tid >> 2, acol = (tid & 3) << 2;
        float4 va = *(const float4*)(Ab + (size_t)arow * D_ + k0 + acol);
        As[acol + 0][arow] = va.x; As[acol + 1][arow] = va.y;
        As[acol + 2][arow] = va.z; As[acol + 3][arow] = va.w;
        int wrow = tid >> 4, wcol = (tid & 15) << 2;
        *(float4*)&Ws[wrow][wcol] = *(const float4*)(W + (k0 + wrow) * 64 + wcol);
        __syncthreads();
        #pragma unroll
        for (int kk = 0; kk < 16; kk++) {
            float a[4], bfr[4];
            *(float4*)a   = *(float4*)&As[kk][ty * 4];
            *(float4*)bfr = *(float4*)&Ws[kk][tx * 4];
            #pragma unroll
            for (int i = 0; i < 4; i++)
                #pragma unroll
                for (int j = 0; j < 4; j++)
                    c[i][j] += a[i] * bfr[j];
        }
        __syncthreads();
    }
    #pragma unroll
    for (int i = 0; i < 4; i++) {
        int m = blockIdx.x * 64 + ty * 4 + i;
        float* orow = out + (size_t)m * D_ + head * 64 + tx * 4;
        #pragma unroll
        for (int j = 0; j < 4; j++) orow[j] = c[i][j];
    }
}

// ---------------- flash attention (no mask, full softmax) ------------------
#define FPAD 65
__global__ __launch_bounds__(256) void flash_kernel(
        const float* __restrict__ Q, const float* __restrict__ K,
        const float* __restrict__ V, float* __restrict__ O) {
    extern __shared__ float sm[];
    float* Qs  = sm;
    float* KVs = sm + 64 * FPAD;
    float* Ps  = sm + 2 * 64 * FPAD;
    int bh = blockIdx.y;
    int b = bh / H_, h = bh % H_;
    size_t base = (size_t)b * S_ * D_ + h * 64;
    int t0 = blockIdx.x * 64;
    int tid = threadIdx.x, ty = tid >> 4, tx = tid & 15;

    for (int i = tid; i < 4096; i += 256) {
        int r = i >> 6, c = i & 63;
        Qs[r * FPAD + c] = Q[base + (size_t)(t0 + r) * D_ + c];
    }
    float acc[4][4] = {};
    float rM[4], rL[4];
    #pragma unroll
    for (int i = 0; i < 4; i++) { rM[i] = -1e30f; rL[i] = 0.f; }

    for (int kt = 0; kt < 16; kt++) {
        __syncthreads();
        int k0 = kt * 64;
        for (int i = tid; i < 4096; i += 256) {
            int r = i >> 6, c = i & 63;
            KVs[r * FPAD + c] = K[base + (size_t)(k0 + r) * D_ + c];
        }
        __syncthreads();
        float sc[4][4] = {};
        #pragma unroll 8
        for (int kk = 0; kk < 64; kk++) {
            float qr[4], kr[4];
            #pragma unroll
            for (int i = 0; i < 4; i++) qr[i] = Qs[(ty + 16 * i) * FPAD + kk];
            #pragma unroll
            for (int j = 0; j < 4; j++) kr[j] = KVs[(tx + 16 * j) * FPAD + kk];
            #pragma unroll
            for (int i = 0; i < 4; i++)
                #pragma unroll
                for (int j = 0; j < 4; j++)
                    sc[i][j] += qr[i] * kr[j];
        }
        #pragma unroll
        for (int i = 0; i < 4; i++)
            #pragma unroll
            for (int j = 0; j < 4; j++)
                sc[i][j] *= 0.125f;
        // online softmax
        float tmax[4];
        #pragma unroll
        for (int i = 0; i < 4; i++) {
            float m = sc[i][0];
            #pragma unroll
            for (int j = 1; j < 4; j++) m = fmaxf(m, sc[i][j]);
            #pragma unroll
            for (int o = 8; o > 0; o >>= 1)
                m = fmaxf(m, __shfl_xor_sync(0xffffffffu, m, o));
            tmax[i] = m;
        }
        float al[4], tsum[4];
        #pragma unroll
        for (int i = 0; i < 4; i++) {
            float nM = fmaxf(rM[i], tmax[i]);
            al[i] = expf(rM[i] - nM);
            rM[i] = nM;
            float ls = 0.f;
            #pragma unroll
            for (int j = 0; j < 4; j++) {
                float p = expf(sc[i][j] - nM);
                Ps[(ty + 16 * i) * FPAD + tx + 16 * j] = p;
                ls += p;
            }
            #pragma unroll
            for (int o = 8; o > 0; o >>= 1)
                ls += __shfl_xor_sync(0xffffffffu, ls, o);
            tsum[i] = ls;
        }
        #pragma unroll
        for (int i = 0; i < 4; i++) {
            rL[i] = rL[i] * al[i] + tsum[i];
            #pragma unroll
            for (int j = 0; j < 4; j++) acc[i][j] *= al[i];
        }
        __syncthreads();
        for (int i = tid; i < 4096; i += 256) {
            int r = i >> 6, c = i & 63;
            KVs[r * FPAD + c] = V[base + (size_t)(k0 + r) * D_ + c];
        }
        __syncthreads();
        #pragma unroll 8
        for (int n = 0; n < 64; n++) {
            float pr[4], vr[4];
            #pragma unroll
            for (int i = 0; i < 4; i++) pr[i] = Ps[(ty + 16 * i) * FPAD + n];
            #pragma unroll
            for (int j = 0; j < 4; j++) vr[j] = KVs[n * FPAD + tx + 16 * j];
            #pragma unroll
            for (int i = 0; i < 4; i++)
                #pragma unroll
                for (int j = 0; j < 4; j++)
                    acc[i][j] += pr[i] * vr[j];
        }
    }
    #pragma unroll
    for (int i = 0; i < 4; i++) {
        float inv = 1.f / rL[i];
        #pragma unroll
        for (int j = 0; j < 4; j++)
            O[base + (size_t)(t0 + ty + 16 * i) * D_ + tx + 16 * j] = acc[i][j] * inv;
    }
}

// ================= TF32 tensor-core GEMM ===================================
// C[M,N] = A[M,K] @ B[K,N] + bias, row-major fp32 in/out.
// EPI: 0 = store, 1 = gelu(tanh) store, 2 = add into C (residual)
#define BM 128
#define BN 128
#define BKK 32
#define AST 36            // BK + 4 pad (A stored [m][k])
#define BST 132           // BN + 4 pad (B stored [k][n])
#define ASZ (BM * AST)    // 4608 floats
#define BSZ (BKK * BST)   // 4224 floats
#define GEMM_SMEM ((2 * ASZ + 2 * BSZ) * 4)   // 70656 bytes

__device__ __forceinline__ unsigned f2tf32(float f) {
    unsigned u;
    asm("cvt.rna.tf32.f32 %0, %1;" : "=r"(u) : "f"(f));
    return u;
}

__device__ __forceinline__ void mma_tf32(float* c, const unsigned* a,
                                         const unsigned* b) {
    asm volatile(
        "mma.sync.aligned.m16n8k8.row.col.f32.tf32.tf32.f32 "
        "{%0,%1,%2,%3}, {%4,%5,%6,%7}, {%8,%9}, {%0,%1,%2,%3};"
        : "+f"(c[0]), "+f"(c[1]), "+f"(c[2]), "+f"(c[3])
        : "r"(a[0]), "r"(a[1]), "r"(a[2]), "r"(a[3]), "r"(b[0]), "r"(b[1]));
}

__device__ __forceinline__ void cp16(unsigned smem_dst, const float* gsrc) {
    asm volatile("cp.async.cg.shared.global [%0], [%1], 16;\n"
                 :: "r"(smem_dst), "l"(gsrc));
}

__device__ __forceinline__ float gelu_tanh(float v) {
    float t = 0.7978845608028654f * (v + 0.044715f * v * v * v);
    return 0.5f * v * (1.f + tanhf(t));
}

template <int EPI>
__global__ __launch_bounds__(256) void gemm_tf32_kernel(
        const float* __restrict__ A, const float* __restrict__ Bm,
        const float* __restrict__ bias, float* __restrict__ C,
        int N, int K) {
    extern __shared__ float sm[];
    float* As = sm;                 // [2][BM][AST]
    float* Bs = sm + 2 * ASZ;       // [2][BK][BST]
    unsigned As_u = (unsigned)__cvta_generic_to_shared(As);
    unsigned Bs_u = (unsigned)__cvta_generic_to_shared(Bs);

    const int tid = threadIdx.x;
    const int warp = tid >> 5, lane = tid & 31;
    const int wm = warp >> 1, wn = warp & 1;
    const int gid = lane >> 2, tig = lane & 3;

    const float* Ab = A + (size_t)blockIdx.x * BM * K;
    const float* Bb = Bm + (size_t)blockIdx.y * BN;

    // cp.async coordinates (4 x 16B chunks each for A and B)
    const int am  = tid >> 3, akc = (tid & 7) << 2;
    const int bk  = tid >> 5, bnc = (tid & 31) << 2;

    const int Kt = K / BKK;
    float acc[2][8][4] = {};

    // prologue: load tile 0 into buf 0
    {
        #pragma unroll
        for (int i = 0; i < 4; i++) {
            int m = am + 32 * i;
            cp16(As_u + (m * AST + akc) * 4, Ab + (size_t)m * K + akc);
        }
        #pragma unroll
        for (int i = 0; i < 4; i++) {
            int k = bk + 8 * i;
            cp16(Bs_u + (k * BST + bnc) * 4, Bb + (size_t)k * N + bnc);
        }
        asm volatile("cp.async.commit_group;\n" ::);
    }

    for (int t = 0; t < Kt; t++) {
        if (t + 1 < Kt) {
            int k0 = (t + 1) * BKK;
            int buf = (t + 1) & 1;
            #pragma unroll
            for (int i = 0; i < 4; i++) {
                int m = am + 32 * i;
                cp16(As_u + (buf * ASZ + m * AST + akc) * 4,
                     Ab + (size_t)m * K + k0 + akc);
            }
            #pragma unroll
            for (int i = 0; i < 4; i++) {
                int k = bk + 8 * i;
                cp16(Bs_u + (buf * BSZ + k * BST + bnc) * 4,
                     Bb + (size_t)(k0 + k) * N + bnc);
            }
        }
        asm volatile("cp.async.commit_group;\n" ::);
        asm volatile("cp.async.wait_group 1;\n" ::);
        __syncthreads();

        const float* Ac = As + (t & 1) * ASZ;
        const float* Bc = Bs + (t & 1) * BSZ;
        #pragma unroll
        for (int ks = 0; ks < 4; ks++) {
            unsigned af[2][4];
            #pragma unroll
            for (int mt = 0; mt < 2; mt++) {
                const float* ap = Ac + (wm * 32 + mt * 16 + gid) * AST + ks * 8 + tig;
                af[mt][0] = f2tf32(ap[0]);
                af[mt][1] = f2tf32(ap[8 * AST]);
                af[mt][2] = f2tf32(ap[4]);
                af[mt][3] = f2tf32(ap[8 * AST + 4]);
            }
            unsigned bf[8][2];
            #pragma unroll
            for (int nt = 0; nt < 8; nt++) {
                const float* bp = Bc + (ks * 8 + tig) * BST + wn * 64 + nt * 8 + gid;
                bf[nt][0] = f2tf32(bp[0]);
                bf[nt][1] = f2tf32(bp[4 * BST]);
            }
            #pragma unroll
            for (int mt = 0; mt < 2; mt++)
                #pragma unroll
                for (int nt = 0; nt < 8; nt++)
                    mma_tf32(acc[mt][nt], af[mt], bf[nt]);
        }
        __syncthreads();
    }

    // epilogue
    #pragma unroll
    for (int mt = 0; mt < 2; mt++) {
        int m0 = blockIdx.x * BM + wm * 32 + mt * 16 + gid;
        #pragma unroll
        for (int nt = 0; nt < 8; nt++) {
            int n0 = blockIdx.y * BN + wn * 64 + nt * 8 + 2 * tig;
            float bx = bias[n0], by = bias[n0 + 1];
            float v0 = acc[mt][nt][0] + bx;
            float v1 = acc[mt][nt][1] + by;
            float v2 = acc[mt][nt][2] + bx;
            float v3 = acc[mt][nt][3] + by;
            float2* p0 = (float2*)(C + (size_t)m0 * N + n0);
            float2* p1 = (float2*)(C + (size_t)(m0 + 8) * N + n0);
            if (EPI == 0) {
                *p0 = make_float2(v0, v1);
                *p1 = make_float2(v2, v3);
            } else if (EPI == 1) {
                *p0 = make_float2(gelu_tanh(v0), gelu_tanh(v1));
                *p1 = make_float2(gelu_tanh(v2), gelu_tanh(v3));
            } else {
                float2 o0 = *p0, o1 = *p1;
                *p0 = make_float2(o0.x + v0, o0.y + v1);
                *p1 = make_float2(o1.x + v2, o1.y + v3);
            }
        }
    }
}

// ---------------- host driver ----------------------------------------------
extern "C" void kernel_launch(void* const* d_in, const int* in_sizes, int n_in,
                              void* d_out, int out_size) {
    const int*   tokens  = (const int*)d_in[0];
    const int*   actions = (const int*)d_in[1];
    const float* emb     = (const float*)d_in[2];
    const float* act_emb = (const float*)d_in[3];
    const float* ln1_g   = (const float*)d_in[4];
    const float* ln1_b   = (const float*)d_in[5];
    const float* Wq      = (const float*)d_in[6];
    const float* Wk      = (const float*)d_in[7];
    const float* Wv      = (const float*)d_in[8];
    const float* Wo      = (const float*)d_in[9];
    const float* bo      = (const float*)d_in[10];
    const float* ln2_g   = (const float*)d_in[11];
    const float* ln2_b   = (const float*)d_in[12];
    const float* W1      = (const float*)d_in[13];
    const float* b1      = (const float*)d_in[14];
    const float* W2      = (const float*)d_in[15];
    const float* b2      = (const float*)d_in[16];
    const float* lnf_g   = (const float*)d_in[17];
    const float* lnf_b   = (const float*)d_in[18];
    const float* Wout    = (const float*)d_in[19];
    const float* bout    = (const float*)d_in[20];
    float* out = (float*)d_out;

    float *x, *h, *q, *k, *v, *o, *mlp, *a, *g, *bb;
    cudaGetSymbolAddress((void**)&x,  d_x);
    cudaGetSymbolAddress((void**)&h,  d_h);
    cudaGetSymbolAddress((void**)&q,  d_q);
    cudaGetSymbolAddress((void**)&k,  d_k);
    cudaGetSymbolAddress((void**)&v,  d_v);
    cudaGetSymbolAddress((void**)&o,  d_o);
    cudaGetSymbolAddress((void**)&mlp, d_mlp);
    cudaGetSymbolAddress((void**)&a,  d_a);
    cudaGetSymbolAddress((void**)&g,  d_g);
    cudaGetSymbolAddress((void**)&bb, d_bb);

    const int flash_smem = 3 * 64 * FPAD * (int)sizeof(float);  // 49920
    cudaFuncSetAttribute(flash_kernel,
                         cudaFuncAttributeMaxDynamicSharedMemorySize, flash_smem);
    cudaFuncSetAttribute(gemm_tf32_kernel<0>,
                         cudaFuncAttributeMaxDynamicSharedMemorySize, GEMM_SMEM);
    cudaFuncSetAttribute(gemm_tf32_kernel<1>,
                         cudaFuncAttributeMaxDynamicSharedMemorySize, GEMM_SMEM);
    cudaFuncSetAttribute(gemm_tf32_kernel<2>,
                         cudaFuncAttributeMaxDynamicSharedMemorySize, GEMM_SMEM);

    embed_kernel<<<BS_, 256>>>(tokens, emb, x);
    act_kernel<<<B_, 256>>>(actions, act_emb, a);

    const int lnSz  = COND_ * D_;        // 196608
    const int wqSz  = H_ * DH_ * DH_;    // 49152
    const int woSz  = D_ * D_;           // 589824
    const int w1Sz  = D_ * 4 * D_;       // 2359296

    const dim3 cmGrid(D_ / 256, B_);

    for (int l = 0; l < L_; l++) {
        condmod_kernel<<<cmGrid, 256>>>(a, ln1_g + (size_t)l * lnSz,
                                        ln1_b + (size_t)l * lnSz, g, bb);
        ln_kernel<<<BS_, 256>>>(x, g, bb, h);
        qkv_kernel<<<dim3(BS_ / 64, H_, 3), 256>>>(
            h, Wq + (size_t)l * wqSz, Wk + (size_t)l * wqSz,
            Wv + (size_t)l * wqSz, q, k, v);
        flash_kernel<<<dim3(S_ / 64, B_ * H_), 256, flash_smem>>>(q, k, v, o);
        gemm_tf32_kernel<2><<<dim3(BS_ / 128, D_ / 128), 256, GEMM_SMEM>>>(
            o, Wo + (size_t)l * woSz, bo + (size_t)l * D_, x, D_, D_);
        condmod_kernel<<<cmGrid, 256>>>(a, ln2_g + (size_t)l * lnSz,
                                        ln2_b + (size_t)l * lnSz, g, bb);
        ln_kernel<<<BS_, 256>>>(x, g, bb, h);
        gemm_tf32_kernel<1><<<dim3(BS_ / 128, 4 * D_ / 128), 256, GEMM_SMEM>>>(
            h, W1 + (size_t)l * w1Sz, b1 + (size_t)l * 4 * D_, mlp, 4 * D_, D_);
        gemm_tf32_kernel<2><<<dim3(BS_ / 128, D_ / 128), 256, GEMM_SMEM>>>(
            mlp, W2 + (size_t)l * w1Sz, b2 + (size_t)l * D_, x, D_, 4 * D_);
    }
    condmod_kernel<<<cmGrid, 256>>>(a, lnf_g, lnf_b, g, bb);
    ln_kernel<<<BS_, 256>>>(x, g, bb, h);
    gemm_tf32_kernel<0><<<dim3(BS_ / 128, V_ / 128), 256, GEMM_SMEM>>>(
        h, Wout, bout, out, V_, D_);
}